// round 1
// baseline (speedup 1.0000x reference)
#include <cuda_runtime.h>
#include <cstdint>
#include <cstddef>

#define DIM       256
#define TM        128
#define KT        16
#define NTHREADS  256
#define XS_STRIDE 260
#define WS_STRIDE 264
#define WS_BUF    (KT*WS_STRIDE)      /* 4224 floats per buffer */
#define NEG_SLOPE 0.01f

/* smem layout in floats */
#define XS_OFF 0
#define WS_OFF (TM*XS_STRIDE)                 /* 33280 */
#define B1_OFF (WS_OFF + 2*WS_BUF)            /* 41728 */
#define AUX_OFF (B1_OFF + 256)                /* 41984 */
#define SMEM_FLOATS (AUX_OFF + 256)           /* 42240 -> 168960 bytes */

/* ---------- packed f32x2 helpers (sm_100+ PTX) ---------- */
__device__ __forceinline__ unsigned long long pack2(float lo, float hi) {
    unsigned long long r;
    asm("mov.b64 %0, {%1, %2};" : "=l"(r) : "r"(__float_as_uint(lo)), "r"(__float_as_uint(hi)));
    return r;
}
__device__ __forceinline__ void unpack2(unsigned long long v, float& lo, float& hi) {
    unsigned int a, b;
    asm("mov.b64 {%0, %1}, %2;" : "=r"(a), "=r"(b) : "l"(v));
    lo = __uint_as_float(a); hi = __uint_as_float(b);
}
__device__ __forceinline__ void fma2(unsigned long long& acc, unsigned long long a, unsigned long long b) {
    asm("fma.rn.f32x2 %0, %1, %2, %0;" : "+l"(acc) : "l"(a), "l"(b));
}
__device__ __forceinline__ float lrelu(float x) {
    return fmaxf(x, 0.f) + NEG_SLOPE * fminf(x, 0.f);
}

/* ---------- weight tile staging: global [N][256] row-major -> smem [kk][n^swz] ---------- */
template<int ROUNDS>
__device__ __forceinline__ void ldg_wtile(float4* pre, const float* __restrict__ W,
                                          int k0, int nvalid, int tid) {
    int kq = tid & 3;
    int nb = tid >> 2;              /* 0..63 */
#pragma unroll
    for (int r = 0; r < ROUNDS; r++) {
        int n = nb + 64 * r;
        if (n < nvalid) pre[r] = *(const float4*)(W + (size_t)n * DIM + k0 + 4 * kq);
        else            pre[r] = make_float4(0.f, 0.f, 0.f, 0.f);
    }
}
template<int ROUNDS>
__device__ __forceinline__ void sts_wtile(float* Ws, const float4* pre, int tid) {
    int kq = tid & 3;
    int nb = tid >> 2;
#pragma unroll
    for (int r = 0; r < ROUNDS; r++) {
        int n = nb + 64 * r;
        const float* v = (const float*)&pre[r];
#pragma unroll
        for (int j = 0; j < 4; j++) {
            int kk = 4 * kq + j;
            int ph = n ^ (4 * (kk & 7));         /* bank swizzle */
            Ws[kk * WS_STRIDE + ph] = v[j];
        }
    }
}

/* ---------- inner GEMM tile: C[8m x (NJ*64?) ...] rows m0..m0+7, n = 4tx+64j+i ---------- */
template<int NJ>
__device__ __forceinline__ void gemm_tile(const float* __restrict__ Xs,
                                          const float* __restrict__ Ws,
                                          int m0, int tx, int t,
                                          unsigned long long (&acc)[4][NJ * 4]) {
#pragma unroll
    for (int kk = 0; kk < KT; kk++) {
        int k = t * KT + kk;
        float xf[8];
#pragma unroll
        for (int i = 0; i < 8; i++) xf[i] = Xs[(m0 + i) * XS_STRIDE + k];
        unsigned long long xp[4];
#pragma unroll
        for (int p = 0; p < 4; p++) xp[p] = pack2(xf[2 * p], xf[2 * p + 1]);
        int q = (4 * tx) ^ (4 * (kk & 7));
#pragma unroll
        for (int j = 0; j < NJ; j++) {
            float4 w = *(const float4*)(Ws + kk * WS_STRIDE + q + 64 * j);
            const float* wf = (const float*)&w;
#pragma unroll
            for (int i = 0; i < 4; i++) {
                unsigned long long bb = pack2(wf[i], wf[i]);
#pragma unroll
                for (int p = 0; p < 4; p++) fma2(acc[p][4 * j + i], xp[p], bb);
            }
        }
    }
}

/* ---------- gathered X load: 128 rows of 256 fp32 into Xs[m][k] ---------- */
__device__ __forceinline__ void gather_row(float* Xs, const float* __restrict__ atom,
                                           int m, int g, int q) {
    const float4* src = (const float4*)(atom + (size_t)g * DIM);
#pragma unroll
    for (int c = 0; c < 8; c++) {
        int k4 = c * 8 + q;
        *(float4*)&Xs[m * XS_STRIDE + 4 * k4] = src[k4];
    }
}

/* ================= STEM HEAD ================= */
__global__ void __launch_bounds__(NTHREADS, 1)
stems_kernel(const float* __restrict__ atom,
             const float* __restrict__ w1, const float* __restrict__ b1,
             const float* __restrict__ w2, const float* __restrict__ b2,
             const int* __restrict__ slices, const int* __restrict__ st_batch,
             const int* __restrict__ st_atom, float* __restrict__ out) {
    extern __shared__ float sm[];
    float* Xs  = sm + XS_OFF;
    float* Ws  = sm + WS_OFF;
    float* b1s = sm + B1_OFF;
    float* b2s = sm + AUX_OFF;
    int tid = threadIdx.x, blk = blockIdx.x;

    b1s[tid] = b1[tid];
    if (tid < 128) b2s[tid] = (tid < 105) ? b2[tid] : 0.f;

    { /* gather */
        int lane = tid & 31, warp = tid >> 5;
        int mrow = lane >> 3, q = lane & 7;
#pragma unroll
        for (int rr = 0; rr < 16; rr += 4) {
            int m  = warp * 16 + rr + mrow;
            int mg = blk * TM + m;
            int g  = slices[st_batch[mg]] + st_atom[mg];
            gather_row(Xs, atom, m, g, q);
        }
    }

    int tx = tid & 15, ty = tid >> 4;
    int m0 = ty * 8;

    float4 pre[4];
    ldg_wtile<4>(pre, w1, 0, 256, tid);
    sts_wtile<4>(Ws, pre, tid);
    __syncthreads();

    unsigned long long acc1[4][16];
#pragma unroll
    for (int j = 0; j < 4; j++)
#pragma unroll
        for (int i = 0; i < 4; i++) {
            float bv = b1s[4 * tx + 64 * j + i];
            unsigned long long pv = pack2(bv, bv);
#pragma unroll
            for (int p = 0; p < 4; p++) acc1[p][4 * j + i] = pv;
        }

#pragma unroll 1
    for (int t = 0; t < 16; t++) {
        if (t < 15) ldg_wtile<4>(pre, w1, (t + 1) * KT, 256, tid);
        gemm_tile<4>(Xs, Ws + (t & 1) * WS_BUF, m0, tx, t, acc1);
        if (t < 15) sts_wtile<4>(Ws + ((t + 1) & 1) * WS_BUF, pre, tid);
        __syncthreads();
    }

    /* H = LeakyReLU(acc1) overwrites Xs (all GEMM1 reads done: loop-final sync) */
#pragma unroll
    for (int p = 0; p < 4; p++)
#pragma unroll
        for (int j4 = 0; j4 < 16; j4++) {
            int n = 4 * tx + 64 * (j4 >> 2) + (j4 & 3);
            float lo, hi; unpack2(acc1[p][j4], lo, hi);
            Xs[(m0 + 2 * p)     * XS_STRIDE + n] = lrelu(lo);
            Xs[(m0 + 2 * p + 1) * XS_STRIDE + n] = lrelu(hi);
        }

    float4 pre2[2];
    ldg_wtile<2>(pre2, w2, 0, 105, tid);
    sts_wtile<2>(Ws, pre2, tid);
    __syncthreads();

    unsigned long long acc2[4][8];
#pragma unroll
    for (int j = 0; j < 2; j++)
#pragma unroll
        for (int i = 0; i < 4; i++) {
            float bv = b2s[4 * tx + 64 * j + i];
            unsigned long long pv = pack2(bv, bv);
#pragma unroll
            for (int p = 0; p < 4; p++) acc2[p][4 * j + i] = pv;
        }

#pragma unroll 1
    for (int t = 0; t < 16; t++) {
        if (t < 15) ldg_wtile<2>(pre2, w2, (t + 1) * KT, 105, tid);
        gemm_tile<2>(Xs, Ws + (t & 1) * WS_BUF, m0, tx, t, acc2);
        if (t < 15) sts_wtile<2>(Ws + ((t + 1) & 1) * WS_BUF, pre2, tid);
        __syncthreads();
    }

    size_t rbase = (size_t)blk * TM;
#pragma unroll
    for (int p = 0; p < 4; p++)
#pragma unroll
        for (int j4 = 0; j4 < 8; j4++) {
            int n = 4 * tx + 64 * (j4 >> 2) + (j4 & 3);
            if (n < 105) {
                float lo, hi; unpack2(acc2[p][j4], lo, hi);
                out[(rbase + m0 + 2 * p)     * 105 + n] = lo;
                out[(rbase + m0 + 2 * p + 1) * 105 + n] = hi;
            }
        }
}

/* ================= BOND HEAD ================= */
__global__ void __launch_bounds__(NTHREADS, 1)
bonds_kernel(const float* __restrict__ atom,
             const float* __restrict__ w1, const float* __restrict__ b1,
             const float* __restrict__ w2, const float* __restrict__ b2,
             const int* __restrict__ slices, const int* __restrict__ bd_batch,
             const int* __restrict__ bonds, float* __restrict__ out) {
    extern __shared__ float sm[];
    float* Xs  = sm + XS_OFF;
    float* Ws  = sm + WS_OFF;
    float* b1s = sm + B1_OFF;
    float* w2s = sm + AUX_OFF;
    int tid = threadIdx.x, blk = blockIdx.x;

    b1s[tid] = b1[tid];
    w2s[tid] = w2[tid];

    { /* gather: row r -> bond r/2 endpoint r%2 */
        int lane = tid & 31, warp = tid >> 5;
        int mrow = lane >> 3, q = lane & 7;
#pragma unroll
        for (int rr = 0; rr < 16; rr += 4) {
            int m  = warp * 16 + rr + mrow;
            int mg = blk * TM + m;
            int bd = mg >> 1, e = mg & 1;
            int g  = slices[bd_batch[bd]] + bonds[2 * bd + e];
            gather_row(Xs, atom, m, g, q);
        }
    }

    int tx = tid & 15, ty = tid >> 4;
    int m0 = ty * 8;

    float4 pre[4];
    ldg_wtile<4>(pre, w1, 0, 256, tid);
    sts_wtile<4>(Ws, pre, tid);
    __syncthreads();

    unsigned long long acc1[4][16];
#pragma unroll
    for (int j = 0; j < 4; j++)
#pragma unroll
        for (int i = 0; i < 4; i++) {
            float bv = b1s[4 * tx + 64 * j + i];
            unsigned long long pv = pack2(bv, bv);
#pragma unroll
            for (int p = 0; p < 4; p++) acc1[p][4 * j + i] = pv;
        }

#pragma unroll 1
    for (int t = 0; t < 16; t++) {
        if (t < 15) ldg_wtile<4>(pre, w1, (t + 1) * KT, 256, tid);
        gemm_tile<4>(Xs, Ws + (t & 1) * WS_BUF, m0, tx, t, acc1);
        if (t < 15) sts_wtile<4>(Ws + ((t + 1) & 1) * WS_BUF, pre, tid);
        __syncthreads();
    }

    /* second layer is a dot with w2: reduce in registers + half-warp shuffle */
    float yp[8];
#pragma unroll
    for (int i = 0; i < 8; i++) yp[i] = 0.f;
#pragma unroll
    for (int p = 0; p < 4; p++)
#pragma unroll
        for (int j4 = 0; j4 < 16; j4++) {
            int n = 4 * tx + 64 * (j4 >> 2) + (j4 & 3);
            float w = w2s[n];
            float lo, hi; unpack2(acc1[p][j4], lo, hi);
            yp[2 * p]     += lrelu(lo) * w;
            yp[2 * p + 1] += lrelu(hi) * w;
        }
#pragma unroll
    for (int off = 8; off >= 1; off >>= 1)
#pragma unroll
        for (int i = 0; i < 8; i++)
            yp[i] += __shfl_xor_sync(0xffffffffu, yp[i], off);

    if (tx == 0) {
        float b2v = b2[0];
        int bond0 = (blk * TM + m0) >> 1;     /* 4 bonds per 8 rows */
#pragma unroll
        for (int bnd = 0; bnd < 4; bnd++)
            out[bond0 + bnd] = 0.5f * (yp[2 * bnd] + yp[2 * bnd + 1]) + b2v;
    }
}

/* ================= launch ================= */
extern "C" void kernel_launch(void* const* d_in, const int* in_sizes, int n_in,
                              void* d_out, int out_size) {
    const float* atom = (const float*)d_in[0];
    const float* mol  = (const float*)d_in[1];
    const float* w_s1 = (const float*)d_in[2];
    const float* b_s1 = (const float*)d_in[3];
    const float* w_s2 = (const float*)d_in[4];
    const float* b_s2 = (const float*)d_in[5];
    const float* w_b1 = (const float*)d_in[6];
    const float* b_b1 = (const float*)d_in[7];
    const float* w_b2 = (const float*)d_in[8];
    const float* b_b2 = (const float*)d_in[9];
    const int* slices = (const int*)d_in[10];
    const int* st_b   = (const int*)d_in[11];
    const int* st_a   = (const int*)d_in[12];
    const int* bonds  = (const int*)d_in[13];
    const int* bd_b   = (const int*)d_in[14];

    int n_stems = in_sizes[11];
    int n_mol   = in_sizes[1];
    int n_bonds = in_sizes[14];

    float* out       = (float*)d_out;
    float* out_stem  = out;
    float* out_mol   = out + (size_t)n_stems * 105;
    float* out_bond  = out_mol + n_mol;

    size_t smem = (size_t)SMEM_FLOATS * sizeof(float);
    cudaFuncSetAttribute(stems_kernel, cudaFuncAttributeMaxDynamicSharedMemorySize, (int)smem);
    cudaFuncSetAttribute(bonds_kernel, cudaFuncAttributeMaxDynamicSharedMemorySize, (int)smem);

    cudaMemcpyAsync(out_mol, mol, (size_t)n_mol * sizeof(float), cudaMemcpyDeviceToDevice);

    bonds_kernel<<<(2 * n_bonds) / TM, NTHREADS, smem>>>(
        atom, w_b1, b_b1, w_b2, b_b2, slices, bd_b, bonds, out_bond);
    stems_kernel<<<n_stems / TM, NTHREADS, smem>>>(
        atom, w_s1, b_s1, w_s2, b_s2, slices, st_b, st_a, out_stem);
}